// round 16
// baseline (speedup 1.0000x reference)
#include <cuda_runtime.h>
#include <cuda_bf16.h>
#include <cstdint>

#define BB 4
#define NN 1024
#define DD 768
#define HH 12
#define HD 64
#define BH 48
#define KTH 104857

// ---------------- scratch ----------------
__device__ float g_qkv[4096 * 2304];
__device__ float g_attn[(size_t)48 * 1024 * 1024];
__device__ float g_ao[4096 * 768];
__device__ unsigned g_hist[48 * 2048];
__device__ unsigned g_sel[48];
__device__ int g_krem[48];
__device__ float g_thr[48];
__device__ unsigned g_cand[(size_t)48 * 1048576];
__device__ int g_bcnt[48 * 32];
__device__ float g_rowm[48 * 1024];
__device__ float g_rowinv[48 * 1024];

__device__ __forceinline__ unsigned fkey(float f) {
    unsigned u = __float_as_uint(f);
    return (u & 0x80000000u) ? ~u : (u ^ 0x80000000u);
}

// ---------------- bf16 mma / ldmatrix helpers ----------------
__device__ __forceinline__ void mma_bf16(float* c, unsigned a0, unsigned a1,
                                         unsigned a2, unsigned a3,
                                         unsigned b0, unsigned b1) {
    asm volatile(
        "mma.sync.aligned.m16n8k16.row.col.f32.bf16.bf16.f32 "
        "{%0,%1,%2,%3}, {%4,%5,%6,%7}, {%8,%9}, {%0,%1,%2,%3};"
        : "+f"(c[0]), "+f"(c[1]), "+f"(c[2]), "+f"(c[3])
        : "r"(a0), "r"(a1), "r"(a2), "r"(a3), "r"(b0), "r"(b1));
}
__device__ __forceinline__ void ldm_x4(unsigned& r0, unsigned& r1, unsigned& r2,
                                       unsigned& r3, unsigned addr) {
    asm volatile(
        "ldmatrix.sync.aligned.m8n8.x4.shared.b16 {%0,%1,%2,%3}, [%4];"
        : "=r"(r0), "=r"(r1), "=r"(r2), "=r"(r3) : "r"(addr));
}

// pair split: (x,y) -> hi bf16x2 + lo bf16x2 (identical rounding to scalar path)
__device__ __forceinline__ void split2v(float x, float y, __nv_bfloat162& hp,
                                        __nv_bfloat162& lp) {
    hp = __floats2bfloat162_rn(x, y);
    float2 hf = __bfloat1622float2(hp);
    lp = __floats2bfloat162_rn(x - hf.x, y - hf.y);
}

// ---------------------------------------------------------------------------
// Split-bf16 tensor-core GEMM. R15 structure + ldmatrix fragment loads
// (smem stride 24 bf16 = 48 B rows; 16B-aligned, conflict-free ldmatrix).
// C[m,n] = scale * sum_k A[m,k]*Bop[k,n] (+bias)
// A: [M][K] k-contig. If TRANSB: B global is [K][N] n-contig (weights / V).
// Else: B global is [N][K] k-contig (scores). NT = N block tile.
// SMAX: A is raw scores; apply masked softmax inline using per-row stats.
// HIST: bin epilogue values into per-bh pass-0 histogram.
// Block tile 128 x NT, BK=16, 256 threads (8 warps of 64 x NT/4).
// ---------------------------------------------------------------------------
template <int NT, bool TRANSB, bool BIAS, bool SCALE, bool SMAX, bool HIST>
__global__ void __launch_bounds__(256) mma_gemm(
    const float* __restrict__ A, size_t azb, size_t azh, int lda,
    const float* __restrict__ B, size_t bzb, size_t bzh, int ldb,
    const float* __restrict__ bias, float* __restrict__ C,
    size_t czb, size_t czh, int ldc, int K, float scale) {
    constexpr int NI = NT / 32;
    constexpr int ST = 24;                       // smem row stride (bf16)
    __shared__ __align__(16) __nv_bfloat16 Ah[128][ST], Al[128][ST];
    __shared__ __align__(16) __nv_bfloat16 Bhs[NT][ST], Bls[NT][ST];
    __shared__ unsigned hsm[HIST ? 2048 : 1];

    int t = threadIdx.x, lane = t & 31, warp = t >> 5;
    int z = blockIdx.z, zb = z / HH, zh = z % HH;
    A += (size_t)zb * azb + (size_t)zh * azh;
    B += (size_t)zb * bzb + (size_t)zh * bzh;
    C += (size_t)zb * czb + (size_t)zh * czh;
    int n0 = blockIdx.x * NT, m0 = blockIdx.y * 128;
    int wm = (warp >> 2) * 64, wn = (warp & 3) * (NT / 4);

    if (HIST)
        for (int j = t; j < 2048; j += 256) hsm[j] = 0u;

    int arow = t >> 1, akc = (t & 1) * 8;

    // ---- loop-invariant ldmatrix addresses (smem contents change, addrs don't)
    unsigned ah_b = (unsigned)__cvta_generic_to_shared(&Ah[0][0]);
    unsigned al_b = (unsigned)__cvta_generic_to_shared(&Al[0][0]);
    unsigned bh_b = (unsigned)__cvta_generic_to_shared(&Bhs[0][0]);
    unsigned bl_b = (unsigned)__cvta_generic_to_shared(&Bls[0][0]);
    int a_r = lane & 15, a_c = (lane & 16) ? 8 : 0;       // A lane mapping
    int b_r = (lane & 7) + ((lane & 16) ? 8 : 0);         // B lane mapping
    int b_c = (lane & 8) ? 8 : 0;
    unsigned aoff[4], boff[NI / 2];
#pragma unroll
    for (int mi = 0; mi < 4; mi++)
        aoff[mi] = (unsigned)(((wm + mi * 16 + a_r) * ST + a_c) * 2);
#pragma unroll
    for (int nj = 0; nj < NI / 2; nj++)
        boff[nj] = (unsigned)(((wn + nj * 16 + b_r) * ST + b_c) * 2);

    // per-row softmax stats (loop-invariant: this thread stages row m0+arow)
    float s_thr = 0.f, s_m = 0.f, s_inv = 0.f;
    if (SMAX) {
        s_thr = g_thr[z];
        int grow = z * NN + m0 + arow;
        s_m = g_rowm[grow];
        s_inv = g_rowinv[grow];
    }

    float c[4][NI][4];
#pragma unroll
    for (int mi = 0; mi < 4; mi++)
#pragma unroll
        for (int ni = 0; ni < NI; ni++)
#pragma unroll
            for (int q = 0; q < 4; q++) c[mi][ni][q] = 0.f;

    for (int kt = 0; kt < K; kt += 16) {
        // ---- stage A: 128 x 16, split hi/lo, bf16x2 vectorized stores
        {
            const float* Ap = A + (size_t)(m0 + arow) * lda + kt + akc;
            float4 v0 = *(const float4*)Ap;
            float4 v1 = *(const float4*)(Ap + 4);
            float vv[8] = {v0.x, v0.y, v0.z, v0.w, v1.x, v1.y, v1.z, v1.w};
            if (SMAX) {
#pragma unroll
                for (int j = 0; j < 8; j++) {
                    float vm = (vv[j] <= s_thr) ? -1e9f : vv[j];
                    vv[j] = __expf(vm - s_m) * s_inv;
                }
            }
#pragma unroll
            for (int j = 0; j < 8; j += 2) {
                __nv_bfloat162 hp, lp;
                split2v(vv[j], vv[j + 1], hp, lp);
                *(__nv_bfloat162*)&Ah[arow][akc + j] = hp;
                *(__nv_bfloat162*)&Al[arow][akc + j] = lp;
            }
        }
        // ---- stage B
        if (TRANSB) {
            constexpr int PER = NT / 16;      // 8 (NT=128) or 4 (NT=64)
            int kr = t >> 4, nc = (t & 15) * PER;
            const float* Bp = B + (size_t)(kt + kr) * ldb + n0 + nc;
#pragma unroll
            for (int j4 = 0; j4 < PER; j4 += 4) {
                float4 v = *(const float4*)(Bp + j4);
                float vv[4] = {v.x, v.y, v.z, v.w};
#pragma unroll
                for (int j = 0; j < 4; j++) {
                    __nv_bfloat16 h = __float2bfloat16(vv[j]);
                    Bhs[nc + j4 + j][kr] = h;
                    Bls[nc + j4 + j][kr] =
                        __float2bfloat16(vv[j] - __bfloat162float(h));
                }
            }
        } else {
            // NT == 128: B global [N][K] k-contig, bf16x2 vectorized stores
            int row = t >> 1, kc = (t & 1) * 8;
            const float* Bp = B + (size_t)(n0 + row) * ldb + kt + kc;
            float4 v0 = *(const float4*)Bp;
            float4 v1 = *(const float4*)(Bp + 4);
            float vv[8] = {v0.x, v0.y, v0.z, v0.w, v1.x, v1.y, v1.z, v1.w};
#pragma unroll
            for (int j = 0; j < 8; j += 2) {
                __nv_bfloat162 hp, lp;
                split2v(vv[j], vv[j + 1], hp, lp);
                *(__nv_bfloat162*)&Bhs[row][kc + j] = hp;
                *(__nv_bfloat162*)&Bls[row][kc + j] = lp;
            }
        }
        __syncthreads();

        // ---- fragments via ldmatrix + mma
        unsigned bfh[NI][2], bfl[NI][2];
#pragma unroll
        for (int nj = 0; nj < NI; nj += 2) {
            ldm_x4(bfh[nj][0], bfh[nj][1], bfh[nj + 1][0], bfh[nj + 1][1],
                   bh_b + boff[nj >> 1]);
            ldm_x4(bfl[nj][0], bfl[nj][1], bfl[nj + 1][0], bfl[nj + 1][1],
                   bl_b + boff[nj >> 1]);
        }
#pragma unroll
        for (int mi = 0; mi < 4; mi++) {
            unsigned a0h, a1h, a2h, a3h, a0l, a1l, a2l, a3l;
            ldm_x4(a0h, a1h, a2h, a3h, ah_b + aoff[mi]);
            ldm_x4(a0l, a1l, a2l, a3l, al_b + aoff[mi]);
#pragma unroll
            for (int ni = 0; ni < NI; ni++) {
                mma_bf16(c[mi][ni], a0h, a1h, a2h, a3h, bfh[ni][0], bfh[ni][1]);
                mma_bf16(c[mi][ni], a0h, a1h, a2h, a3h, bfl[ni][0], bfl[ni][1]);
                mma_bf16(c[mi][ni], a0l, a1l, a2l, a3l, bfh[ni][0], bfh[ni][1]);
            }
        }
        __syncthreads();
    }

    // ---- epilogue
#pragma unroll
    for (int mi = 0; mi < 4; mi++) {
        int r = m0 + wm + mi * 16 + (lane >> 2);
#pragma unroll
        for (int ni = 0; ni < NI; ni++) {
            int col = n0 + wn + ni * 8 + (lane & 3) * 2;
            float2 v0 = {c[mi][ni][0], c[mi][ni][1]};
            float2 v1 = {c[mi][ni][2], c[mi][ni][3]};
            if (SCALE) {
                v0.x *= scale; v0.y *= scale;
                v1.x *= scale; v1.y *= scale;
            }
            if (BIAS) {
                float2 bb = *(const float2*)(bias + col);
                v0.x += bb.x; v0.y += bb.y;
                v1.x += bb.x; v1.y += bb.y;
            }
            if (HIST) {
                atomicAdd(&hsm[fkey(v0.x) >> 21], 1u);
                atomicAdd(&hsm[fkey(v0.y) >> 21], 1u);
                atomicAdd(&hsm[fkey(v1.x) >> 21], 1u);
                atomicAdd(&hsm[fkey(v1.y) >> 21], 1u);
            }
            *(float2*)(C + (size_t)r * ldc + col) = v0;
            *(float2*)(C + (size_t)(r + 8) * ldc + col) = v1;
        }
    }
    if (HIST) {
        __syncthreads();
        unsigned* gh = g_hist + z * 2048;
        for (int j = t; j < 2048; j += 256) {
            unsigned cc = hsm[j];
            if (cc) atomicAdd(&gh[j], cc);
        }
    }
}

// ---------------------------------------------------------------------------
// Selection: init -> scan0 -> segmented cand gather -> final select
// ---------------------------------------------------------------------------
__global__ void sel_init() {
    int bh = blockIdx.x, t = threadIdx.x;
    for (int j = t; j < 2048; j += 256) g_hist[bh * 2048 + j] = 0u;
}

__global__ void scan0() {
    int bh = blockIdx.x, t = threadIdx.x;
    __shared__ unsigned ssum[256];
    __shared__ int s_sel;
    __shared__ unsigned s_kin;
    const unsigned* hist = g_hist + bh * 2048;
    unsigned loc[8], lsum = 0;
#pragma unroll
    for (int i = 0; i < 8; i++) { loc[i] = hist[t * 8 + i]; lsum += loc[i]; }
    ssum[t] = lsum;
    __syncthreads();
    if (t == 0) {
        unsigned k = KTH, cum = 0, kin = k;
        int sel = 255;
        for (int i = 0; i < 256; i++) {
            if (cum + ssum[i] >= k) { sel = i; kin = k - cum; break; }
            cum += ssum[i];
        }
        s_sel = sel; s_kin = kin;
    }
    __syncthreads();
    if (t == s_sel) {
        unsigned kk = s_kin, cum = 0, d = t * 8 + 7, knew = kk;
#pragma unroll
        for (int i = 0; i < 8; i++) {
            if (cum + loc[i] >= kk) { d = t * 8 + i; knew = kk - cum; break; }
            cum += loc[i];
        }
        g_sel[bh] = d;
        g_krem[bh] = (int)knew;
    }
}

__global__ void cand_seg() {
    __shared__ int s_cnt;
    int bh = blockIdx.y, t = threadIdx.x;
    unsigned lane = t & 31;
    if (t == 0) s_cnt = 0;
    __syncthreads();
    unsigned sel = g_sel[bh];
    unsigned* seg = g_cand + (size_t)bh * 1048576 + (size_t)blockIdx.x * 32768;
    const float4* Sp = (const float4*)(g_attn + (size_t)bh * 1048576) +
                       (size_t)blockIdx.x * 8192;
    for (int i = 0; i < 32; i++) {
        float4 v = Sp[i * 256 + t];
        unsigned key[4] = {fkey(v.x), fkey(v.y), fkey(v.z), fkey(v.w)};
#pragma unroll
        for (int j = 0; j < 4; j++) {
            bool m = (key[j] >> 21) == sel;
            unsigned bal = __ballot_sync(0xffffffffu, m);
            if (bal) {
                int leader = __ffs(bal) - 1;
                int base = 0;
                if ((int)lane == leader) base = atomicAdd(&s_cnt, __popc(bal));
                base = __shfl_sync(0xffffffffu, base, leader);
                if (m) seg[base + __popc(bal & ((1u << lane) - 1u))] = key[j];
            }
        }
    }
    __syncthreads();
    if (t == 0) g_bcnt[bh * 32 + blockIdx.x] = s_cnt;
}

__global__ void sel_final() {
    int bh = blockIdx.x, t = threadIdx.x;
    __shared__ unsigned sh[2048];
    __shared__ unsigned ssum[256];
    __shared__ int s_sel;
    __shared__ unsigned s_kin;
    __shared__ unsigned s_b1, s_k2;
    const unsigned* base = g_cand + (size_t)bh * 1048576;

    // pass A: bits 20..10
    for (int j = t; j < 2048; j += 256) sh[j] = 0u;
    __syncthreads();
    for (int sg = 0; sg < 32; sg++) {
        int cnt = g_bcnt[bh * 32 + sg];
        const unsigned* cand = base + (size_t)sg * 32768;
        for (int i = t; i < cnt; i += 256)
            atomicAdd(&sh[(cand[i] >> 10) & 2047u], 1u);
    }
    __syncthreads();
    {
        unsigned loc[8], lsum = 0;
#pragma unroll
        for (int i = 0; i < 8; i++) { loc[i] = sh[t * 8 + i]; lsum += loc[i]; }
        ssum[t] = lsum;
        __syncthreads();
        if (t == 0) {
            unsigned k = (unsigned)g_krem[bh], cum = 0, kin = k;
            int sel = 255;
            for (int i = 0; i < 256; i++) {
                if (cum + ssum[i] >= k) { sel = i; kin = k - cum; break; }
                cum += ssum[i];
            }
            s_sel = sel; s_kin = kin;
        }
        __syncthreads();
        if (t == s_sel) {
            unsigned kk = s_kin, cum = 0, d = t * 8 + 7, knew = kk;
#pragma unroll
            for (int i = 0; i < 8; i++) {
                if (cum + loc[i] >= kk) { d = t * 8 + i; knew = kk - cum; break; }
                cum += loc[i];
            }
            s_b1 = d; s_k2 = knew;
        }
        __syncthreads();
    }
    unsigned b1 = s_b1;
    __syncthreads();

    // pass B: bits 9..0
    for (int j = t; j < 1024; j += 256) sh[j] = 0u;
    __syncthreads();
    for (int sg = 0; sg < 32; sg++) {
        int cnt = g_bcnt[bh * 32 + sg];
        const unsigned* cand = base + (size_t)sg * 32768;
        for (int i = t; i < cnt; i += 256) {
            unsigned ky = cand[i];
            if (((ky >> 10) & 2047u) == b1) atomicAdd(&sh[ky & 1023u], 1u);
        }
    }
    __syncthreads();
    {
        unsigned loc[4], lsum = 0;
#pragma unroll
        for (int i = 0; i < 4; i++) { loc[i] = sh[t * 4 + i]; lsum += loc[i]; }
        ssum[t] = lsum;
        __syncthreads();
        if (t == 0) {
            unsigned k = s_k2, cum = 0, kin = k;
            int sel = 255;
            for (int i = 0; i < 256; i++) {
                if (cum + ssum[i] >= k) { sel = i; kin = k - cum; break; }
                cum += ssum[i];
            }
            s_sel = sel; s_kin = kin;
        }
        __syncthreads();
        if (t == s_sel) {
            unsigned kk = s_kin, cum = 0, d = t * 4 + 3;
#pragma unroll
            for (int i = 0; i < 4; i++) {
                if (cum + loc[i] >= kk) { d = t * 4 + i; break; }
                cum += loc[i];
            }
            unsigned key = (g_sel[bh] << 21) | (b1 << 10) | d;
            unsigned bits = (key & 0x80000000u) ? (key ^ 0x80000000u) : ~key;
            g_thr[bh] = __uint_as_float(bits);
        }
    }
}

// ---------------------------------------------------------------------------
// Row stats: per-row (max, 1/sum); AV applies the softmax inline.
// ---------------------------------------------------------------------------
__global__ void rowstats() {
    int row = blockIdx.x, bh = row >> 10;
    float thr = g_thr[bh];
    const float4* S = (const float4*)(g_attn + (size_t)row * NN);
    int t = threadIdx.x;
    unsigned lane = t & 31, w = t >> 5;
    __shared__ float red[8];

    float4 vv = S[t];
    float v[4] = {vv.x, vv.y, vv.z, vv.w};
    float mx = -3.0e38f;
#pragma unroll
    for (int i = 0; i < 4; i++) {
        v[i] = (v[i] <= thr) ? -1e9f : v[i];
        mx = fmaxf(mx, v[i]);
    }
#pragma unroll
    for (int o = 16; o; o >>= 1) mx = fmaxf(mx, __shfl_xor_sync(0xffffffffu, mx, o));
    if (lane == 0) red[w] = mx;
    __syncthreads();
    float m = red[0];
#pragma unroll
    for (int i = 1; i < 8; i++) m = fmaxf(m, red[i]);

    float s = 0.f;
#pragma unroll
    for (int i = 0; i < 4; i++) s += __expf(v[i] - m);
#pragma unroll
    for (int o = 16; o; o >>= 1) s += __shfl_xor_sync(0xffffffffu, s, o);
    __syncthreads();
    if (lane == 0) red[w] = s;
    __syncthreads();
    if (t == 0) {
        float tot = 0.f;
#pragma unroll
        for (int i = 0; i < 8; i++) tot += red[i];
        g_rowm[row] = m;
        g_rowinv[row] = 1.f / tot;
    }
}

// ---------------------------------------------------------------------------
extern "C" void kernel_launch(void* const* d_in, const int* in_sizes, int n_in,
                              void* d_out, int out_size) {
    const float* x = (const float*)d_in[0];
    const float* W_qkv = (const float*)d_in[1];
    const float* b_qkv = (const float*)d_in[2];
    const float* W_out = (const float*)d_in[3];
    const float* b_out = (const float*)d_in[4];
    float* out = (float*)d_out;

    float* qkv_p; cudaGetSymbolAddress((void**)&qkv_p, g_qkv);
    float* attn_p; cudaGetSymbolAddress((void**)&attn_p, g_attn);
    float* ao_p;  cudaGetSymbolAddress((void**)&ao_p, g_ao);

    // 0. zero hist
    sel_init<<<BH, 256>>>();
    // 1. QKV projection: [4096,768] @ W[768,2304] + bias
    mma_gemm<128, true, true, false, false, false><<<dim3(18, 32, 1), 256>>>(
        x, 0, 0, 768, W_qkv, 0, 0, 2304, b_qkv, qkv_p, 0, 0, 2304, 768, 1.f);
    // 2. Scores: Q @ K^T * 0.125  (+ fused pass-0 histogram)
    mma_gemm<128, false, false, true, false, true><<<dim3(8, 8, BH), 256>>>(
        qkv_p, (size_t)1024 * 2304, 64, 2304,
        qkv_p + 768, (size_t)1024 * 2304, 64, 2304,
        nullptr, attn_p, (size_t)HH * 1048576, 1048576, 1024, 64, 0.125f);
    // 3. Threshold: scan + segmented candidate gather + final select
    scan0<<<BH, 256>>>();
    cand_seg<<<dim3(32, BH), 256>>>();
    sel_final<<<BH, 256>>>();
    // 4. Per-row softmax stats (no P materialization)
    rowstats<<<BH * NN, 256>>>();
    // 5. P @ V with softmax fused into A staging
    mma_gemm<64, true, false, false, true, false><<<dim3(1, 8, BH), 256>>>(
        attn_p, (size_t)HH * 1048576, 1048576, 1024,
        qkv_p + 1536, (size_t)1024 * 2304, 64, 2304,
        nullptr, ao_p, (size_t)1024 * 768, 64, 768, 1024, 1.f);
    // 6. Output projection: [4096,768] @ W[768,768] + bias
    mma_gemm<128, true, true, false, false, false><<<dim3(6, 32, 1), 256>>>(
        ao_p, 0, 0, 768, W_out, 0, 0, 768, b_out, out, 0, 0, 768, 768, 1.f);
}

// round 17
// speedup vs baseline: 1.2095x; 1.2095x over previous
#include <cuda_runtime.h>
#include <cuda_bf16.h>
#include <cstdint>

#define BB 4
#define NN 1024
#define DD 768
#define HH 12
#define HD 64
#define BH 48
#define KTH 104857

// ---------------- scratch ----------------
__device__ float g_qkv[4096 * 2304];
__device__ float g_attn[(size_t)48 * 1024 * 1024];
__device__ float g_ao[4096 * 768];
__device__ unsigned g_hist[48 * 2048];
__device__ unsigned g_sel[48];
__device__ int g_krem[48];
__device__ float g_thr[48];
__device__ unsigned g_cand[(size_t)48 * 1048576];
__device__ int g_bcnt[48 * 32];
__device__ float g_rowm[48 * 1024];
__device__ float g_rowinv[48 * 1024];

__device__ __forceinline__ unsigned fkey(float f) {
    unsigned u = __float_as_uint(f);
    return (u & 0x80000000u) ? ~u : (u ^ 0x80000000u);
}

// ---------------- bf16 mma helpers ----------------
__device__ __forceinline__ void mma_bf16(float* c, unsigned a0, unsigned a1,
                                         unsigned a2, unsigned a3,
                                         unsigned b0, unsigned b1) {
    asm volatile(
        "mma.sync.aligned.m16n8k16.row.col.f32.bf16.bf16.f32 "
        "{%0,%1,%2,%3}, {%4,%5,%6,%7}, {%8,%9}, {%0,%1,%2,%3};"
        : "+f"(c[0]), "+f"(c[1]), "+f"(c[2]), "+f"(c[3])
        : "r"(a0), "r"(a1), "r"(a2), "r"(a3), "r"(b0), "r"(b1));
}

// pair split: (x,y) -> hi bf16x2 + lo bf16x2 (identical rounding to scalar path)
__device__ __forceinline__ void split2v(float x, float y, __nv_bfloat162& hp,
                                        __nv_bfloat162& lp) {
    hp = __floats2bfloat162_rn(x, y);
    float2 hf = __bfloat1622float2(hp);
    lp = __floats2bfloat162_rn(x - hf.x, y - hf.y);
}

// ---------------------------------------------------------------------------
// Split-bf16 tensor-core GEMM (R15 proven mainloop, stride 18, scalar frag
// loads, vectorized bf16x2 staging stores).
// C[m,n] = scale * sum_k A[m,k]*Bop[k,n] (+bias)
// A: [M][K] k-contig. If TRANSB: B global is [K][N] n-contig (weights / V).
// Else: B global is [N][K] k-contig (scores). NT = N block tile.
// SMAX: A is raw scores; apply masked softmax inline using per-row stats.
// HIST: bin epilogue values into per-bh pass-0 histogram.
// KSPLIT: blockIdx.x selects a K-chunk (K passed = chunk size); epilogue
//         accumulates into C via atomicAdd (C pre-zeroed).
// Block tile 128 x NT, BK=16, 256 threads (8 warps of 64 x NT/4).
// ---------------------------------------------------------------------------
template <int NT, bool TRANSB, bool BIAS, bool SCALE, bool SMAX, bool HIST,
          bool KSPLIT>
__global__ void __launch_bounds__(256) mma_gemm(
    const float* __restrict__ A, size_t azb, size_t azh, int lda,
    const float* __restrict__ B, size_t bzb, size_t bzh, int ldb,
    const float* __restrict__ bias, float* __restrict__ C,
    size_t czb, size_t czh, int ldc, int K, float scale) {
    constexpr int NI = NT / 32;
    __shared__ __nv_bfloat16 Ah[128][18], Al[128][18];
    __shared__ __nv_bfloat16 Bhs[NT][18], Bls[NT][18];
    __shared__ unsigned hsm[HIST ? 2048 : 1];

    int t = threadIdx.x, lane = t & 31, warp = t >> 5;
    int z = blockIdx.z, zb = z / HH, zh = z % HH;
    A += (size_t)zb * azb + (size_t)zh * azh;
    B += (size_t)zb * bzb + (size_t)zh * bzh;
    C += (size_t)zb * czb + (size_t)zh * czh;
    int n0 = KSPLIT ? 0 : blockIdx.x * NT;
    int m0 = blockIdx.y * 128;
    if (KSPLIT) {
        int kc = blockIdx.x;          // k-chunk index
        A += (size_t)kc * K;          // A k-contig
        B += (size_t)kc * K * (TRANSB ? ldb : 1);
    }
    int wm = (warp >> 2) * 64, wn = (warp & 3) * (NT / 4);

    if (HIST)
        for (int j = t; j < 2048; j += 256) hsm[j] = 0u;

    int arow = t >> 1, akc = (t & 1) * 8;

    // per-row softmax stats (loop-invariant: this thread stages row m0+arow)
    float s_thr = 0.f, s_m = 0.f, s_inv = 0.f;
    if (SMAX) {
        s_thr = g_thr[z];
        int grow = z * NN + m0 + arow;
        s_m = g_rowm[grow];
        s_inv = g_rowinv[grow];
    }

    float c[4][NI][4];
#pragma unroll
    for (int mi = 0; mi < 4; mi++)
#pragma unroll
        for (int ni = 0; ni < NI; ni++)
#pragma unroll
            for (int q = 0; q < 4; q++) c[mi][ni][q] = 0.f;

    for (int kt = 0; kt < K; kt += 16) {
        // ---- stage A: 128 x 16, split hi/lo, bf16x2 vectorized stores
        {
            const float* Ap = A + (size_t)(m0 + arow) * lda + kt + akc;
            float4 v0 = *(const float4*)Ap;
            float4 v1 = *(const float4*)(Ap + 4);
            float vv[8] = {v0.x, v0.y, v0.z, v0.w, v1.x, v1.y, v1.z, v1.w};
            if (SMAX) {
#pragma unroll
                for (int j = 0; j < 8; j++) {
                    float vm = (vv[j] <= s_thr) ? -1e9f : vv[j];
                    vv[j] = __expf(vm - s_m) * s_inv;
                }
            }
#pragma unroll
            for (int j = 0; j < 8; j += 2) {
                __nv_bfloat162 hp, lp;
                split2v(vv[j], vv[j + 1], hp, lp);
                *(__nv_bfloat162*)&Ah[arow][akc + j] = hp;
                *(__nv_bfloat162*)&Al[arow][akc + j] = lp;
            }
        }
        // ---- stage B
        if (TRANSB) {
            constexpr int PER = NT / 16;      // 8 (NT=128) or 4 (NT=64)
            int kr = t >> 4, nc = (t & 15) * PER;
            const float* Bp = B + (size_t)(kt + kr) * ldb + n0 + nc;
#pragma unroll
            for (int j4 = 0; j4 < PER; j4 += 4) {
                float4 v = *(const float4*)(Bp + j4);
                float vv[4] = {v.x, v.y, v.z, v.w};
#pragma unroll
                for (int j = 0; j < 4; j++) {
                    __nv_bfloat16 h = __float2bfloat16(vv[j]);
                    Bhs[nc + j4 + j][kr] = h;
                    Bls[nc + j4 + j][kr] =
                        __float2bfloat16(vv[j] - __bfloat162float(h));
                }
            }
        } else {
            // NT == 128: B global [N][K] k-contig, bf16x2 vectorized stores
            int row = t >> 1, kc = (t & 1) * 8;
            const float* Bp = B + (size_t)(n0 + row) * ldb + kt + kc;
            float4 v0 = *(const float4*)Bp;
            float4 v1 = *(const float4*)(Bp + 4);
            float vv[8] = {v0.x, v0.y, v0.z, v0.w, v1.x, v1.y, v1.z, v1.w};
#pragma unroll
            for (int j = 0; j < 8; j += 2) {
                __nv_bfloat162 hp, lp;
                split2v(vv[j], vv[j + 1], hp, lp);
                *(__nv_bfloat162*)&Bhs[row][kc + j] = hp;
                *(__nv_bfloat162*)&Bls[row][kc + j] = lp;
            }
        }
        __syncthreads();

        // ---- fragments + mma
        unsigned bfh[NI][2], bfl[NI][2];
        int kk = (lane & 3) * 2;
#pragma unroll
        for (int ni = 0; ni < NI; ni++) {
            int n = wn + ni * 8 + (lane >> 2);
            bfh[ni][0] = *(const unsigned*)&Bhs[n][kk];
            bfh[ni][1] = *(const unsigned*)&Bhs[n][kk + 8];
            bfl[ni][0] = *(const unsigned*)&Bls[n][kk];
            bfl[ni][1] = *(const unsigned*)&Bls[n][kk + 8];
        }
#pragma unroll
        for (int mi = 0; mi < 4; mi++) {
            int r = wm + mi * 16 + (lane >> 2);
            unsigned a0h = *(const unsigned*)&Ah[r][kk];
            unsigned a1h = *(const unsigned*)&Ah[r + 8][kk];
            unsigned a2h = *(const unsigned*)&Ah[r][kk + 8];
            unsigned a3h = *(const unsigned*)&Ah[r + 8][kk + 8];
            unsigned a0l = *(const unsigned*)&Al[r][kk];
            unsigned a1l = *(const unsigned*)&Al[r + 8][kk];
            unsigned a2l = *(const unsigned*)&Al[r][kk + 8];
            unsigned a3l = *(const unsigned*)&Al[r + 8][kk + 8];
#pragma unroll
            for (int ni = 0; ni < NI; ni++) {
                mma_bf16(c[mi][ni], a0h, a1h, a2h, a3h, bfh[ni][0], bfh[ni][1]);
                mma_bf16(c[mi][ni], a0h, a1h, a2h, a3h, bfl[ni][0], bfl[ni][1]);
                mma_bf16(c[mi][ni], a0l, a1l, a2l, a3l, bfh[ni][0], bfh[ni][1]);
            }
        }
        __syncthreads();
    }

    // ---- epilogue
#pragma unroll
    for (int mi = 0; mi < 4; mi++) {
        int r = m0 + wm + mi * 16 + (lane >> 2);
#pragma unroll
        for (int ni = 0; ni < NI; ni++) {
            int col = n0 + wn + ni * 8 + (lane & 3) * 2;
            float2 v0 = {c[mi][ni][0], c[mi][ni][1]};
            float2 v1 = {c[mi][ni][2], c[mi][ni][3]};
            if (SCALE) {
                v0.x *= scale; v0.y *= scale;
                v1.x *= scale; v1.y *= scale;
            }
            if (BIAS) {
                float2 bb = *(const float2*)(bias + col);
                v0.x += bb.x; v0.y += bb.y;
                v1.x += bb.x; v1.y += bb.y;
            }
            if (HIST) {
                atomicAdd(&hsm[fkey(v0.x) >> 21], 1u);
                atomicAdd(&hsm[fkey(v0.y) >> 21], 1u);
                atomicAdd(&hsm[fkey(v1.x) >> 21], 1u);
                atomicAdd(&hsm[fkey(v1.y) >> 21], 1u);
            }
            float* C0 = C + (size_t)r * ldc + col;
            float* C1 = C + (size_t)(r + 8) * ldc + col;
            if (KSPLIT) {
                atomicAdd(C0 + 0, v0.x);
                atomicAdd(C0 + 1, v0.y);
                atomicAdd(C1 + 0, v1.x);
                atomicAdd(C1 + 1, v1.y);
            } else {
                *(float2*)C0 = v0;
                *(float2*)C1 = v1;
            }
        }
    }
    if (HIST) {
        __syncthreads();
        unsigned* gh = g_hist + z * 2048;
        for (int j = t; j < 2048; j += 256) {
            unsigned cc = hsm[j];
            if (cc) atomicAdd(&gh[j], cc);
        }
    }
}

// ---------------------------------------------------------------------------
// zero g_ao (accumulated via atomics by the K-split AV)
// ---------------------------------------------------------------------------
__global__ void zero_ao() {
    int i = blockIdx.x * 256 + threadIdx.x;
    ((float4*)g_ao)[i] = make_float4(0.f, 0.f, 0.f, 0.f);
}

// ---------------------------------------------------------------------------
// Selection: init -> scan0 -> segmented cand gather -> final select
// ---------------------------------------------------------------------------
__global__ void sel_init() {
    int bh = blockIdx.x, t = threadIdx.x;
    for (int j = t; j < 2048; j += 256) g_hist[bh * 2048 + j] = 0u;
}

__global__ void scan0() {
    int bh = blockIdx.x, t = threadIdx.x;
    __shared__ unsigned ssum[256];
    __shared__ int s_sel;
    __shared__ unsigned s_kin;
    const unsigned* hist = g_hist + bh * 2048;
    unsigned loc[8], lsum = 0;
#pragma unroll
    for (int i = 0; i < 8; i++) { loc[i] = hist[t * 8 + i]; lsum += loc[i]; }
    ssum[t] = lsum;
    __syncthreads();
    if (t == 0) {
        unsigned k = KTH, cum = 0, kin = k;
        int sel = 255;
        for (int i = 0; i < 256; i++) {
            if (cum + ssum[i] >= k) { sel = i; kin = k - cum; break; }
            cum += ssum[i];
        }
        s_sel = sel; s_kin = kin;
    }
    __syncthreads();
    if (t == s_sel) {
        unsigned kk = s_kin, cum = 0, d = t * 8 + 7, knew = kk;
#pragma unroll
        for (int i = 0; i < 8; i++) {
            if (cum + loc[i] >= kk) { d = t * 8 + i; knew = kk - cum; break; }
            cum += loc[i];
        }
        g_sel[bh] = d;
        g_krem[bh] = (int)knew;
    }
}

__global__ void cand_seg() {
    __shared__ int s_cnt;
    int bh = blockIdx.y, t = threadIdx.x;
    unsigned lane = t & 31;
    if (t == 0) s_cnt = 0;
    __syncthreads();
    unsigned sel = g_sel[bh];
    unsigned* seg = g_cand + (size_t)bh * 1048576 + (size_t)blockIdx.x * 32768;
    const float4* Sp = (const float4*)(g_attn + (size_t)bh * 1048576) +
                       (size_t)blockIdx.x * 8192;
    for (int i = 0; i < 32; i++) {
        float4 v = Sp[i * 256 + t];
        unsigned key[4] = {fkey(v.x), fkey(v.y), fkey(v.z), fkey(v.w)};
#pragma unroll
        for (int j = 0; j < 4; j++) {
            bool m = (key[j] >> 21) == sel;
            unsigned bal = __ballot_sync(0xffffffffu, m);
            if (bal) {
                int leader = __ffs(bal) - 1;
                int base = 0;
                if ((int)lane == leader) base = atomicAdd(&s_cnt, __popc(bal));
                base = __shfl_sync(0xffffffffu, base, leader);
                if (m) seg[base + __popc(bal & ((1u << lane) - 1u))] = key[j];
            }
        }
    }
    __syncthreads();
    if (t == 0) g_bcnt[bh * 32 + blockIdx.x] = s_cnt;
}

__global__ void sel_final() {
    int bh = blockIdx.x, t = threadIdx.x;
    __shared__ unsigned sh[2048];
    __shared__ unsigned ssum[256];
    __shared__ int s_sel;
    __shared__ unsigned s_kin;
    __shared__ unsigned s_b1, s_k2;
    const unsigned* base = g_cand + (size_t)bh * 1048576;

    // pass A: bits 20..10
    for (int j = t; j < 2048; j += 256) sh[j] = 0u;
    __syncthreads();
    for (int sg = 0; sg < 32; sg++) {
        int cnt = g_bcnt[bh * 32 + sg];
        const unsigned* cand = base + (size_t)sg * 32768;
        for (int i = t; i < cnt; i += 256)
            atomicAdd(&sh[(cand[i] >> 10) & 2047u], 1u);
    }
    __syncthreads();
    {
        unsigned loc[8], lsum = 0;
#pragma unroll
        for (int i = 0; i < 8; i++) { loc[i] = sh[t * 8 + i]; lsum += loc[i]; }
        ssum[t] = lsum;
        __syncthreads();
        if (t == 0) {
            unsigned k = (unsigned)g_krem[bh], cum = 0, kin = k;
            int sel = 255;
            for (int i = 0; i < 256; i++) {
                if (cum + ssum[i] >= k) { sel = i; kin = k - cum; break; }
                cum += ssum[i];
            }
            s_sel = sel; s_kin = kin;
        }
        __syncthreads();
        if (t == s_sel) {
            unsigned kk = s_kin, cum = 0, d = t * 8 + 7, knew = kk;
#pragma unroll
            for (int i = 0; i < 8; i++) {
                if (cum + loc[i] >= kk) { d = t * 8 + i; knew = kk - cum; break; }
                cum += loc[i];
            }
            s_b1 = d; s_k2 = knew;
        }
        __syncthreads();
    }
    unsigned b1 = s_b1;
    __syncthreads();

    // pass B: bits 9..0
    for (int j = t; j < 1024; j += 256) sh[j] = 0u;
    __syncthreads();
    for (int sg = 0; sg < 32; sg++) {
        int cnt = g_bcnt[bh * 32 + sg];
        const unsigned* cand = base + (size_t)sg * 32768;
        for (int i = t; i < cnt; i += 256) {
            unsigned ky = cand[i];
            if (((ky >> 10) & 2047u) == b1) atomicAdd(&sh[ky & 1023u], 1u);
        }
    }
    __syncthreads();
    {
        unsigned loc[4], lsum = 0;
#pragma unroll
        for (int i = 0; i < 4; i++) { loc[i] = sh[t * 4 + i]; lsum += loc[i]; }
        ssum[t] = lsum;
        __syncthreads();
        if (t == 0) {
            unsigned k = s_k2, cum = 0, kin = k;
            int sel = 255;
            for (int i = 0; i < 256; i++) {
                if (cum + ssum[i] >= k) { sel = i; kin = k - cum; break; }
                cum += ssum[i];
            }
            s_sel = sel; s_kin = kin;
        }
        __syncthreads();
        if (t == s_sel) {
            unsigned kk = s_kin, cum = 0, d = t * 4 + 3;
#pragma unroll
            for (int i = 0; i < 4; i++) {
                if (cum + loc[i] >= kk) { d = t * 4 + i; break; }
                cum += loc[i];
            }
            unsigned key = (g_sel[bh] << 21) | (b1 << 10) | d;
            unsigned bits = (key & 0x80000000u) ? (key ^ 0x80000000u) : ~key;
            g_thr[bh] = __uint_as_float(bits);
        }
    }
}

// ---------------------------------------------------------------------------
// Row stats: per-row (max, 1/sum); AV applies the softmax inline.
// ---------------------------------------------------------------------------
__global__ void rowstats() {
    int row = blockIdx.x, bh = row >> 10;
    float thr = g_thr[bh];
    const float4* S = (const float4*)(g_attn + (size_t)row * NN);
    int t = threadIdx.x;
    unsigned lane = t & 31, w = t >> 5;
    __shared__ float red[8];

    float4 vv = S[t];
    float v[4] = {vv.x, vv.y, vv.z, vv.w};
    float mx = -3.0e38f;
#pragma unroll
    for (int i = 0; i < 4; i++) {
        v[i] = (v[i] <= thr) ? -1e9f : v[i];
        mx = fmaxf(mx, v[i]);
    }
#pragma unroll
    for (int o = 16; o; o >>= 1) mx = fmaxf(mx, __shfl_xor_sync(0xffffffffu, mx, o));
    if (lane == 0) red[w] = mx;
    __syncthreads();
    float m = red[0];
#pragma unroll
    for (int i = 1; i < 8; i++) m = fmaxf(m, red[i]);

    float s = 0.f;
#pragma unroll
    for (int i = 0; i < 4; i++) s += __expf(v[i] - m);
#pragma unroll
    for (int o = 16; o; o >>= 1) s += __shfl_xor_sync(0xffffffffu, s, o);
    __syncthreads();
    if (lane == 0) red[w] = s;
    __syncthreads();
    if (t == 0) {
        float tot = 0.f;
#pragma unroll
        for (int i = 0; i < 8; i++) tot += red[i];
        g_rowm[row] = m;
        g_rowinv[row] = 1.f / tot;
    }
}

// ---------------------------------------------------------------------------
extern "C" void kernel_launch(void* const* d_in, const int* in_sizes, int n_in,
                              void* d_out, int out_size) {
    const float* x = (const float*)d_in[0];
    const float* W_qkv = (const float*)d_in[1];
    const float* b_qkv = (const float*)d_in[2];
    const float* W_out = (const float*)d_in[3];
    const float* b_out = (const float*)d_in[4];
    float* out = (float*)d_out;

    float* qkv_p; cudaGetSymbolAddress((void**)&qkv_p, g_qkv);
    float* attn_p; cudaGetSymbolAddress((void**)&attn_p, g_attn);
    float* ao_p;  cudaGetSymbolAddress((void**)&ao_p, g_ao);

    // 0. zero hist + ao accumulator
    sel_init<<<BH, 256>>>();
    zero_ao<<<4096 * 768 / 1024, 256>>>();
    // 1. QKV projection: [4096,768] @ W[768,2304] + bias
    mma_gemm<128, true, true, false, false, false, false>
        <<<dim3(18, 32, 1), 256>>>(
        x, 0, 0, 768, W_qkv, 0, 0, 2304, b_qkv, qkv_p, 0, 0, 2304, 768, 1.f);
    // 2. Scores: Q @ K^T * 0.125  (+ fused pass-0 histogram)
    mma_gemm<128, false, false, true, false, true, false>
        <<<dim3(8, 8, BH), 256>>>(
        qkv_p, (size_t)1024 * 2304, 64, 2304,
        qkv_p + 768, (size_t)1024 * 2304, 64, 2304,
        nullptr, attn_p, (size_t)HH * 1048576, 1048576, 1024, 64, 0.125f);
    // 3. Threshold: scan + segmented candidate gather + final select
    scan0<<<BH, 256>>>();
    cand_seg<<<dim3(32, BH), 256>>>();
    sel_final<<<BH, 256>>>();
    // 4. Per-row softmax stats (no P materialization)
    rowstats<<<BH * NN, 256>>>();
    // 5. P @ V with softmax fused into A staging; K split 4-way (atomic acc)
    mma_gemm<64, true, false, false, true, false, true>
        <<<dim3(4, 8, BH), 256>>>(
        attn_p, (size_t)HH * 1048576, 1048576, 1024,
        qkv_p + 1536, (size_t)1024 * 2304, 64, 2304,
        nullptr, ao_p, (size_t)1024 * 768, 64, 768, 256, 1.f);
    // 6. Output projection: [4096,768] @ W[768,768] + bias
    mma_gemm<128, true, true, false, false, false, false>
        <<<dim3(6, 32, 1), 256>>>(
        ao_p, 0, 0, 768, W_out, 0, 0, 768, b_out, out, 0, 0, 768, 768, 1.f);
}